// round 1
// baseline (speedup 1.0000x reference)
#include <cuda_runtime.h>

// Problem constants (shapes fixed by the dataset)
#define Bn   8
#define Hh   80
#define Wd   80
#define Cc   768
#define C3   2304
#define NPOS 6400      // 80*80
#define WIN  14
#define NWIN 6         // ceil(80/14) = 6, Hp=Wp=84
#define LWIN 36        // 6*6 windows
#define NW   196       // 14*14 tokens per window
#define NHD  12        // heads
#define HD   64        // head dim
#define TJ   28        // K/V tile rows (196 = 7*28)

// Scratch (no cudaMalloc allowed): qkv [B,N,3C] fp32, attention output [B,N,C] fp32
__device__ float g_qkv[Bn * NPOS * C3];   // ~472 MB
__device__ float g_att[Bn * NPOS * Cc];   // ~157 MB

// ---------------------------------------------------------------------------
// Classic fp32 SGEMM: C[M,N] = A[M,K] @ B[K,N] (+ bias), 128x128x16 tiles,
// 256 threads, 8x8 per-thread micro-tile. All dims divisible by tile sizes.
// ---------------------------------------------------------------------------
__global__ __launch_bounds__(256) void sgemm128(const float* __restrict__ A,
                                                const float* __restrict__ B,
                                                const float* __restrict__ bias,
                                                float* __restrict__ C,
                                                int M, int N, int K) {
    __shared__ float As[16][128];   // transposed A tile: As[k][m]
    __shared__ float Bs[16][128];   // Bs[k][n]

    const int tid  = threadIdx.x;
    const int brow = blockIdx.y * 128;
    const int bcol = blockIdx.x * 128;
    const int tx   = tid & 15;      // 0..15 -> 8 output cols each
    const int ty   = tid >> 4;      // 0..15 -> 8 output rows each

    float acc[8][8];
#pragma unroll
    for (int i = 0; i < 8; i++)
#pragma unroll
        for (int j = 0; j < 8; j++) acc[i][j] = 0.f;

    const int aRow = tid >> 2;          // 0..63
    const int aCol = (tid & 3) << 2;    // 0,4,8,12
    const int bRow = tid >> 5;          // 0..7
    const int bCol = (tid & 31) << 2;   // 0..124

    for (int kt = 0; kt < K; kt += 16) {
        // Load A tile (128x16), store transposed
#pragma unroll
        for (int r = 0; r < 128; r += 64) {
            float4 a4 = *(const float4*)(A + (size_t)(brow + aRow + r) * K + kt + aCol);
            As[aCol + 0][aRow + r] = a4.x;
            As[aCol + 1][aRow + r] = a4.y;
            As[aCol + 2][aRow + r] = a4.z;
            As[aCol + 3][aRow + r] = a4.w;
        }
        // Load B tile (16x128)
#pragma unroll
        for (int r = 0; r < 16; r += 8) {
            *(float4*)&Bs[bRow + r][bCol] =
                *(const float4*)(B + (size_t)(kt + bRow + r) * N + bcol + bCol);
        }
        __syncthreads();

#pragma unroll
        for (int k = 0; k < 16; k++) {
            float ra[8], rb[8];
#pragma unroll
            for (int i = 0; i < 8; i++) ra[i] = As[k][ty * 8 + i];
#pragma unroll
            for (int j = 0; j < 8; j++) rb[j] = Bs[k][tx * 8 + j];
#pragma unroll
            for (int i = 0; i < 8; i++)
#pragma unroll
                for (int j = 0; j < 8; j++) acc[i][j] += ra[i] * rb[j];
        }
        __syncthreads();
    }

    float bv[8];
#pragma unroll
    for (int j = 0; j < 8; j++)
        bv[j] = (bias != nullptr) ? bias[bcol + tx * 8 + j] : 0.f;

#pragma unroll
    for (int i = 0; i < 8; i++) {
        float* cp = C + (size_t)(brow + ty * 8 + i) * N + bcol + tx * 8;
#pragma unroll
        for (int j = 0; j < 8; j += 4) {
            float4 r;
            r.x = acc[i][j + 0] + bv[j + 0];
            r.y = acc[i][j + 1] + bv[j + 1];
            r.z = acc[i][j + 2] + bv[j + 2];
            r.w = acc[i][j + 3] + bv[j + 3];
            *(float4*)(cp + j) = r;
        }
    }
}

// ---------------------------------------------------------------------------
// Windowed attention: one block per (batch, window, head).
// 224 threads; thread t (< 196) owns query row t. q in registers, K/V tiles
// of 28 rows streamed through smem. Padded tokens (y>=80 or x>=80) are zero
// vectors: zero K rows contribute exp(0) to the softmax denominator (matches
// the reference, which pads qkv with zeros BEFORE softmax). Logits are tiny
// (|s| < ~8 guaranteed statistically, std~0.3), so no max-subtraction needed
// (softmax is shift-invariant).
// ---------------------------------------------------------------------------
__global__ __launch_bounds__(224) void attn_kernel(const float* __restrict__ qkv,
                                                   float* __restrict__ att) {
    __shared__ float ks[TJ][HD];
    __shared__ float vs[TJ][HD];

    const int bid = blockIdx.x;
    const int h   = bid % NHD;
    const int l   = (bid / NHD) % LWIN;
    const int b   = bid / (NHD * LWIN);
    const int wy  = l / NWIN;
    const int wx  = l % NWIN;
    const int t   = threadIdx.x;

    // Load this thread's query row (or zeros if padded / inactive thread)
    float q[HD];
    bool qvalid = false;
    int tok = 0;
    if (t < NW) {
        int ly = t / WIN, lx = t % WIN;
        int gy = wy * WIN + ly, gx = wx * WIN + lx;
        if (gy < Hh && gx < Wd) { qvalid = true; tok = gy * Wd + gx; }
    }
    if (qvalid) {
        const float4* qp = (const float4*)(qkv + ((size_t)b * NPOS + tok) * C3 + h * HD);
#pragma unroll
        for (int d4 = 0; d4 < HD / 4; d4++) {
            float4 v4 = qp[d4];
            q[d4 * 4 + 0] = v4.x; q[d4 * 4 + 1] = v4.y;
            q[d4 * 4 + 2] = v4.z; q[d4 * 4 + 3] = v4.w;
        }
    } else {
#pragma unroll
        for (int d = 0; d < HD; d++) q[d] = 0.f;
    }

    float acc[HD];
#pragma unroll
    for (int d = 0; d < HD; d++) acc[d] = 0.f;
    float lsum = 0.f;

    for (int jt = 0; jt < NW; jt += TJ) {
        __syncthreads();   // previous tile fully consumed
        // Cooperative K/V tile load: 28 rows x 64 floats = 448 float4 per tensor
#pragma unroll
        for (int s = 0; s < 2; s++) {
            int idx = t + s * 224;           // 0..447
            int jj  = idx >> 4;              // row in tile (0..27)
            int c4  = (idx & 15) * 4;        // float offset (0,4,...,60)
            int j   = jt + jj;               // 0..195
            int jy = j / WIN, jx = j % WIN;
            int gy = wy * WIN + jy, gx = wx * WIN + jx;
            float4 kv = make_float4(0.f, 0.f, 0.f, 0.f);
            float4 vv = make_float4(0.f, 0.f, 0.f, 0.f);
            if (gy < Hh && gx < Wd) {
                const float* base = qkv + ((size_t)b * NPOS + gy * Wd + gx) * C3 + h * HD + c4;
                kv = *(const float4*)(base + Cc);        // K slice
                vv = *(const float4*)(base + 2 * Cc);    // V slice
            }
            *(float4*)&ks[jj][c4] = kv;
            *(float4*)&vs[jj][c4] = vv;
        }
        __syncthreads();

        for (int jj = 0; jj < TJ; jj++) {
            float s0 = 0.f, s1 = 0.f, s2 = 0.f, s3 = 0.f;
#pragma unroll
            for (int d = 0; d < HD; d += 4) {
                s0 += q[d + 0] * ks[jj][d + 0];
                s1 += q[d + 1] * ks[jj][d + 1];
                s2 += q[d + 2] * ks[jj][d + 2];
                s3 += q[d + 3] * ks[jj][d + 3];
            }
            float p = __expf(((s0 + s1) + (s2 + s3)) * 0.125f);  // scale = 64^-0.5
            lsum += p;
#pragma unroll
            for (int d = 0; d < HD; d++) acc[d] += p * vs[jj][d];
        }
    }

    if (qvalid) {
        float inv = 1.0f / lsum;
        float* o = att + ((size_t)b * NPOS + tok) * Cc + h * HD;
#pragma unroll
        for (int d = 0; d < HD; d += 4) {
            float4 r;
            r.x = acc[d + 0] * inv; r.y = acc[d + 1] * inv;
            r.z = acc[d + 2] * inv; r.w = acc[d + 3] * inv;
            *(float4*)(o + d) = r;
        }
    }
}

// ---------------------------------------------------------------------------
extern "C" void kernel_launch(void* const* d_in, const int* in_sizes, int n_in,
                              void* d_out, int out_size) {
    const float* x     = (const float*)d_in[0];   // [8, 6400, 768]
    const float* Wqkv  = (const float*)d_in[1];   // [768, 2304]
    const float* Wproj = (const float*)d_in[2];   // [768, 768]
    const float* bproj = (const float*)d_in[3];   // [768]
    float* out = (float*)d_out;                   // [8, 6400, 768]

    float* qkv = nullptr;
    float* att = nullptr;
    cudaGetSymbolAddress((void**)&qkv, g_qkv);
    cudaGetSymbolAddress((void**)&att, g_att);

    const int M = Bn * NPOS;   // 51200

    // 1) QKV projection: [51200,768] @ [768,2304]
    dim3 g1(C3 / 128, M / 128);
    sgemm128<<<g1, 256>>>(x, Wqkv, nullptr, qkv, M, C3, Cc);

    // 2) Windowed attention: one block per (batch, window, head)
    attn_kernel<<<Bn * LWIN * NHD, 224>>>(qkv, att);

    // 3) Output projection + bias: [51200,768] @ [768,768]
    dim3 g2(Cc / 128, M / 128);
    sgemm128<<<g2, 256>>>(att, Wproj, bproj, out, M, Cc, Cc);
}

// round 6
// speedup vs baseline: 1.8659x; 1.8659x over previous
#include <cuda_runtime.h>
#include <cuda_bf16.h>
#include <cstdint>

// Problem constants (shapes fixed by the dataset)
#define Bn   8
#define Hh   80
#define Wd   80
#define Cc   768
#define C3   2304
#define NPOS 6400      // 80*80
#define WIN  14
#define NWIN 6         // ceil(80/14) = 6
#define LWIN 36        // 6*6 windows
#define NW   196       // 14*14 tokens per window
#define NHD  12        // heads
#define HD   64        // head dim
#define TJ   28        // K/V tile rows

// Scratch (no cudaMalloc allowed)
__device__ float g_qkv[Bn * NPOS * C3];   // ~472 MB
__device__ float g_att[Bn * NPOS * Cc];   // ~157 MB

// ---------------------------------------------------------------------------
// Tensor-core GEMM with split-bf16 (hi/lo) emulating ~fp32 precision:
//   C = A @ B (+bias),  acc += Ahi*Bhi + Ahi*Blo + Alo*Bhi  (fp32 accum)
// Tiles: 128x128x32 per CTA, 8 warps each computing 64x32 via m16n8k16 MMA.
// ---------------------------------------------------------------------------
#define BM 128
#define BN 128
#define BK 32
#define AP 40    // A smem row stride (bf16), padded for ldmatrix bank spread
#define BP 136   // B smem row stride (bf16)

__device__ __forceinline__ void ldsm4(uint32_t& r0, uint32_t& r1, uint32_t& r2,
                                      uint32_t& r3, const void* p) {
    uint32_t addr = (uint32_t)__cvta_generic_to_shared(p);
    asm volatile("ldmatrix.sync.aligned.m8n8.x4.shared.b16 {%0,%1,%2,%3}, [%4];"
                 : "=r"(r0), "=r"(r1), "=r"(r2), "=r"(r3) : "r"(addr));
}
__device__ __forceinline__ void ldsm4t(uint32_t& r0, uint32_t& r1, uint32_t& r2,
                                       uint32_t& r3, const void* p) {
    uint32_t addr = (uint32_t)__cvta_generic_to_shared(p);
    asm volatile("ldmatrix.sync.aligned.m8n8.x4.trans.shared.b16 {%0,%1,%2,%3}, [%4];"
                 : "=r"(r0), "=r"(r1), "=r"(r2), "=r"(r3) : "r"(addr));
}
__device__ __forceinline__ void mma16816(float* c, const uint32_t* a, const uint32_t* b) {
    asm volatile("mma.sync.aligned.m16n8k16.row.col.f32.bf16.bf16.f32 "
                 "{%0,%1,%2,%3}, {%4,%5,%6,%7}, {%8,%9}, {%0,%1,%2,%3};"
                 : "+f"(c[0]), "+f"(c[1]), "+f"(c[2]), "+f"(c[3])
                 : "r"(a[0]), "r"(a[1]), "r"(a[2]), "r"(a[3]),
                   "r"(b[0]), "r"(b[1]));
}

__device__ __forceinline__ void split2(float v, __nv_bfloat16& hi, __nv_bfloat16& lo) {
    hi = __float2bfloat16(v);
    lo = __float2bfloat16(v - __bfloat162float(hi));
}

__global__ __launch_bounds__(256, 2) void gemm_split(const float* __restrict__ A,
                                                     const float* __restrict__ B,
                                                     const float* __restrict__ bias,
                                                     float* __restrict__ C,
                                                     int M, int N, int K) {
    __shared__ __nv_bfloat16 Ah[BM * AP];
    __shared__ __nv_bfloat16 Al[BM * AP];
    __shared__ __nv_bfloat16 Bh[BK * BP];
    __shared__ __nv_bfloat16 Bl[BK * BP];

    const int tid  = threadIdx.x;
    const int warp = tid >> 5;
    const int lane = tid & 31;
    const int wm   = (warp >> 2) * 64;   // 0 or 64
    const int wn   = (warp & 3) * 32;    // 0,32,64,96
    const int bm   = blockIdx.y * BM;
    const int bn   = blockIdx.x * BN;

    float acc[4][4][4];
#pragma unroll
    for (int i = 0; i < 4; i++)
#pragma unroll
        for (int j = 0; j < 4; j++)
#pragma unroll
            for (int e = 0; e < 4; e++) acc[i][j][e] = 0.f;

    for (int kt = 0; kt < K; kt += BK) {
        // Stage gmem -> regs (fp32)
        float4 av[4], bv[4];
#pragma unroll
        for (int p = 0; p < 4; p++) {
            int f4 = tid + p * 256;
            int r = f4 >> 3, c = (f4 & 7) << 2;          // A: 128 rows x 8 float4
            av[p] = *(const float4*)(A + (size_t)(bm + r) * K + kt + c);
            int rb = f4 >> 5, cb = (f4 & 31) << 2;       // B: 32 rows x 32 float4
            bv[p] = *(const float4*)(B + (size_t)(kt + rb) * N + bn + cb);
        }
        __syncthreads();   // previous tile fully consumed
        // Split + store to smem
#pragma unroll
        for (int p = 0; p < 4; p++) {
            int f4 = tid + p * 256;
            int r = f4 >> 3, c = (f4 & 7) << 2;
            float va[4] = {av[p].x, av[p].y, av[p].z, av[p].w};
#pragma unroll
            for (int e = 0; e < 4; e++) {
                __nv_bfloat16 hi, lo;
                split2(va[e], hi, lo);
                Ah[r * AP + c + e] = hi;
                Al[r * AP + c + e] = lo;
            }
            int rb = f4 >> 5, cb = (f4 & 31) << 2;
            float vb[4] = {bv[p].x, bv[p].y, bv[p].z, bv[p].w};
#pragma unroll
            for (int e = 0; e < 4; e++) {
                __nv_bfloat16 hi, lo;
                split2(vb[e], hi, lo);
                Bh[rb * BP + cb + e] = hi;
                Bl[rb * BP + cb + e] = lo;
            }
        }
        __syncthreads();

#pragma unroll
        for (int ks = 0; ks < BK; ks += 16) {
            uint32_t ah[4][4], al[4][4];
#pragma unroll
            for (int mt = 0; mt < 4; mt++) {
                const __nv_bfloat16* pa =
                    &Ah[(wm + mt * 16 + (lane & 15)) * AP + ks + ((lane >> 4) << 3)];
                ldsm4(ah[mt][0], ah[mt][1], ah[mt][2], ah[mt][3], pa);
                const __nv_bfloat16* pl =
                    &Al[(wm + mt * 16 + (lane & 15)) * AP + ks + ((lane >> 4) << 3)];
                ldsm4(al[mt][0], al[mt][1], al[mt][2], al[mt][3], pl);
            }
#pragma unroll
            for (int nt2 = 0; nt2 < 2; nt2++) {
                uint32_t bh[4], bl[4];
                const __nv_bfloat16* pb =
                    &Bh[(ks + (lane & 15)) * BP + wn + nt2 * 16 + ((lane >> 4) << 3)];
                ldsm4t(bh[0], bh[1], bh[2], bh[3], pb);
                const __nv_bfloat16* pbl =
                    &Bl[(ks + (lane & 15)) * BP + wn + nt2 * 16 + ((lane >> 4) << 3)];
                ldsm4t(bl[0], bl[1], bl[2], bl[3], pbl);
#pragma unroll
                for (int half = 0; half < 2; half++) {
                    int nt = nt2 * 2 + half;
#pragma unroll
                    for (int mt = 0; mt < 4; mt++) {
                        mma16816(acc[mt][nt], ah[mt], bh + half * 2);
                        mma16816(acc[mt][nt], ah[mt], bl + half * 2);
                        mma16816(acc[mt][nt], al[mt], bh + half * 2);
                    }
                }
            }
        }
    }

    // Epilogue: c0,c1 -> row g; c2,c3 -> row g+8; cols = 2*tg..
    const int g  = lane >> 2;
    const int tg = lane & 3;
#pragma unroll
    for (int nt = 0; nt < 4; nt++) {
        int col = bn + wn + nt * 8 + tg * 2;
        float b0 = (bias != nullptr) ? bias[col] : 0.f;
        float b1 = (bias != nullptr) ? bias[col + 1] : 0.f;
#pragma unroll
        for (int mt = 0; mt < 4; mt++) {
            int r0 = bm + wm + mt * 16 + g;
            float2 v0 = make_float2(acc[mt][nt][0] + b0, acc[mt][nt][1] + b1);
            float2 v1 = make_float2(acc[mt][nt][2] + b0, acc[mt][nt][3] + b1);
            *(float2*)(C + (size_t)r0 * N + col) = v0;
            *(float2*)(C + (size_t)(r0 + 8) * N + col) = v1;
        }
    }
}

// ---------------------------------------------------------------------------
// Windowed attention (unchanged from R1): one block per (batch, window, head).
// ---------------------------------------------------------------------------
__global__ __launch_bounds__(224) void attn_kernel(const float* __restrict__ qkv,
                                                   float* __restrict__ att) {
    __shared__ float ks[TJ][HD];
    __shared__ float vs[TJ][HD];

    const int bid = blockIdx.x;
    const int h   = bid % NHD;
    const int l   = (bid / NHD) % LWIN;
    const int b   = bid / (NHD * LWIN);
    const int wy  = l / NWIN;
    const int wx  = l % NWIN;
    const int t   = threadIdx.x;

    float q[HD];
    bool qvalid = false;
    int tok = 0;
    if (t < NW) {
        int ly = t / WIN, lx = t % WIN;
        int gy = wy * WIN + ly, gx = wx * WIN + lx;
        if (gy < Hh && gx < Wd) { qvalid = true; tok = gy * Wd + gx; }
    }
    if (qvalid) {
        const float4* qp = (const float4*)(qkv + ((size_t)b * NPOS + tok) * C3 + h * HD);
#pragma unroll
        for (int d4 = 0; d4 < HD / 4; d4++) {
            float4 v4 = qp[d4];
            q[d4 * 4 + 0] = v4.x; q[d4 * 4 + 1] = v4.y;
            q[d4 * 4 + 2] = v4.z; q[d4 * 4 + 3] = v4.w;
        }
    } else {
#pragma unroll
        for (int d = 0; d < HD; d++) q[d] = 0.f;
    }

    float acc[HD];
#pragma unroll
    for (int d = 0; d < HD; d++) acc[d] = 0.f;
    float lsum = 0.f;

    for (int jt = 0; jt < NW; jt += TJ) {
        __syncthreads();
#pragma unroll
        for (int s = 0; s < 2; s++) {
            int idx = t + s * 224;
            int jj  = idx >> 4;
            int c4  = (idx & 15) * 4;
            int j   = jt + jj;
            int jy = j / WIN, jx = j % WIN;
            int gy = wy * WIN + jy, gx = wx * WIN + jx;
            float4 kv = make_float4(0.f, 0.f, 0.f, 0.f);
            float4 vv = make_float4(0.f, 0.f, 0.f, 0.f);
            if (gy < Hh && gx < Wd) {
                const float* base = qkv + ((size_t)b * NPOS + gy * Wd + gx) * C3 + h * HD + c4;
                kv = *(const float4*)(base + Cc);
                vv = *(const float4*)(base + 2 * Cc);
            }
            *(float4*)&ks[jj][c4] = kv;
            *(float4*)&vs[jj][c4] = vv;
        }
        __syncthreads();

        for (int jj = 0; jj < TJ; jj++) {
            float s0 = 0.f, s1 = 0.f, s2 = 0.f, s3 = 0.f;
#pragma unroll
            for (int d = 0; d < HD; d += 4) {
                s0 += q[d + 0] * ks[jj][d + 0];
                s1 += q[d + 1] * ks[jj][d + 1];
                s2 += q[d + 2] * ks[jj][d + 2];
                s3 += q[d + 3] * ks[jj][d + 3];
            }
            float p = __expf(((s0 + s1) + (s2 + s3)) * 0.125f);
            lsum += p;
#pragma unroll
            for (int d = 0; d < HD; d++) acc[d] += p * vs[jj][d];
        }
    }

    if (qvalid) {
        float inv = 1.0f / lsum;
        float* o = att + ((size_t)b * NPOS + tok) * Cc + h * HD;
#pragma unroll
        for (int d = 0; d < HD; d += 4) {
            float4 r;
            r.x = acc[d + 0] * inv; r.y = acc[d + 1] * inv;
            r.z = acc[d + 2] * inv; r.w = acc[d + 3] * inv;
            *(float4*)(o + d) = r;
        }
    }
}

// ---------------------------------------------------------------------------
extern "C" void kernel_launch(void* const* d_in, const int* in_sizes, int n_in,
                              void* d_out, int out_size) {
    const float* x     = (const float*)d_in[0];
    const float* Wqkv  = (const float*)d_in[1];
    const float* Wproj = (const float*)d_in[2];
    const float* bproj = (const float*)d_in[3];
    float* out = (float*)d_out;

    float* qkv = nullptr;
    float* att = nullptr;
    cudaGetSymbolAddress((void**)&qkv, g_qkv);
    cudaGetSymbolAddress((void**)&att, g_att);

    const int M = Bn * NPOS;   // 51200

    dim3 g1(C3 / BN, M / BM);
    gemm_split<<<g1, 256>>>(x, Wqkv, nullptr, qkv, M, C3, Cc);

    attn_kernel<<<Bn * LWIN * NHD, 224>>>(qkv, att);

    dim3 g2(Cc / BN, M / BM);
    gemm_split<<<g2, 256>>>(att, Wproj, bproj, out, M, Cc, Cc);
}

// round 12
// speedup vs baseline: 2.3415x; 1.2549x over previous
#include <cuda_runtime.h>
#include <cuda_fp16.h>
#include <cstdint>

// Problem constants
#define Bn   8
#define Hh   80
#define Wd   80
#define Cc   768
#define C3   2304
#define NPOS 6400
#define WIN  14
#define NWIN 6
#define LWIN 36
#define NW   196
#define NHD  12
#define HD   64
#define TJ   28
#define Mrows (Bn * NPOS)   // 51200

// ---------------------------------------------------------------------------
// Scratch (no cudaMalloc allowed)
// ---------------------------------------------------------------------------
__device__ float  g_qkv[(size_t)Mrows * C3];     // 472 MB fp32
__device__ __half g_xh [(size_t)Mrows * Cc];     // x in fp16
__device__ __half g_ahi[(size_t)Mrows * Cc];     // attention out hi
__device__ __half g_alo[(size_t)Mrows * Cc];     // attention out lo
__device__ __half g_wq [(size_t)C3 * Cc];        // Wqkv^T fp16 [2304,768]
__device__ __half g_wph[(size_t)Cc * Cc];        // Wproj^T hi  [768,768]
__device__ __half g_wpl[(size_t)Cc * Cc];        // Wproj^T lo

// ---------------------------------------------------------------------------
// Helpers
// ---------------------------------------------------------------------------
__device__ __forceinline__ uint32_t smem_u32(const void* p) {
    uint32_t a;
    asm("{ .reg .u64 t; cvta.to.shared.u64 t, %1; cvt.u32.u64 %0, t; }" : "=r"(a) : "l"(p));
    return a;
}
__device__ __forceinline__ void ldsm4a(uint32_t* r, uint32_t addr) {
    asm volatile("ldmatrix.sync.aligned.m8n8.x4.shared.b16 {%0,%1,%2,%3}, [%4];"
                 : "=r"(r[0]), "=r"(r[1]), "=r"(r[2]), "=r"(r[3]) : "r"(addr));
}
__device__ __forceinline__ void mma_f16(float* c, const uint32_t* a, const uint32_t* b) {
    asm volatile("mma.sync.aligned.m16n8k16.row.col.f32.f16.f16.f32 "
                 "{%0,%1,%2,%3}, {%4,%5,%6,%7}, {%8,%9}, {%0,%1,%2,%3};"
                 : "+f"(c[0]), "+f"(c[1]), "+f"(c[2]), "+f"(c[3])
                 : "r"(a[0]), "r"(a[1]), "r"(a[2]), "r"(a[3]),
                   "r"(b[0]), "r"(b[1]));
}
__device__ __forceinline__ void cp16(uint32_t dst, const void* src) {
    asm volatile("cp.async.cg.shared.global [%0], [%1], 16;" :: "r"(dst), "l"(src));
}
template <int N>
__device__ __forceinline__ void cp_wait() {
    asm volatile("cp.async.wait_group %0;" :: "n"(N) : "memory");
}
__device__ __forceinline__ void split2h(float v, __half& hi, __half& lo) {
    hi = __float2half(v);
    lo = __float2half(v - __half2float(hi));
}

// ---------------------------------------------------------------------------
// Prep kernels
// ---------------------------------------------------------------------------
__global__ void conv_half(const float* __restrict__ in, __half* __restrict__ out, int n4) {
    int i = blockIdx.x * blockDim.x + threadIdx.x;
    if (i >= n4) return;
    float4 v = ((const float4*)in)[i];
    ((__half2*)out)[i * 2 + 0] = __floats2half2_rn(v.x, v.y);
    ((__half2*)out)[i * 2 + 1] = __floats2half2_rn(v.z, v.w);
}

// W [K,N] fp32 row-major -> T [N,K] fp16 row-major (optional lo)
__global__ void transpose_half(const float* __restrict__ W, __half* __restrict__ Th,
                               __half* __restrict__ Tl, int K, int N) {
    __shared__ float t[32][33];
    int n0 = blockIdx.x * 32, k0 = blockIdx.y * 32;
    int tx = threadIdx.x, ty = threadIdx.y;   // 32 x 8
#pragma unroll
    for (int i = 0; i < 32; i += 8)
        t[ty + i][tx] = W[(size_t)(k0 + ty + i) * N + n0 + tx];
    __syncthreads();
#pragma unroll
    for (int i = 0; i < 32; i += 8) {
        float v = t[tx][ty + i];
        __half hi, lo;
        split2h(v, hi, lo);
        Th[(size_t)(n0 + ty + i) * K + k0 + tx] = hi;
        if (Tl != nullptr) Tl[(size_t)(n0 + ty + i) * K + k0 + tx] = lo;
    }
}

// ---------------------------------------------------------------------------
// fp16 HMMA GEMM: C[M,N] = A[M,K] @ Bt[N,K]^T (+bias), fp32 accum.
// SPLIT==1: single product (Ah*Bh). SPLIT==3: Ah*Bh + Ah*Bl + Al*Bh.
// CTA tile 128x128x32, 8 warps (2x4, warp tile 64x32), cp.async STAGES-deep.
// Smem rows padded to 144B (9 x 16B -> conflict-free ldmatrix, cp16-aligned).
// ---------------------------------------------------------------------------
#define RSB   144                    // bytes per 32-halfword k-row
#define TILEB (128 * RSB)            // 18432 B

template <int SPLIT, int STAGES>
__global__ __launch_bounds__(256)
void gemm_hmma(const __half* __restrict__ Ah, const __half* __restrict__ Al,
               const __half* __restrict__ Bh, const __half* __restrict__ Bl,
               const float* __restrict__ bias, float* __restrict__ C,
               int M, int N, int K) {
    constexpr int NT = (SPLIT == 3) ? 4 : 2;     // tiles per stage
    extern __shared__ char smem[];
    const uint32_t SM_BUF = smem_u32(smem);

    const int tid  = threadIdx.x;
    const int warp = tid >> 5;
    const int lane = tid & 31;
    const int wm   = (warp >> 2) * 64;   // 0 / 64
    const int wn   = (warp & 3) * 32;    // 0,32,64,96
    const int bm   = blockIdx.y * 128;
    const int bn   = blockIdx.x * 128;
    const int nkt  = K / 32;

    float acc[4][4][4];
#pragma unroll
    for (int i = 0; i < 4; i++)
#pragma unroll
        for (int j = 0; j < 4; j++)
#pragma unroll
            for (int e = 0; e < 4; e++) acc[i][j][e] = 0.f;

    // ---- stage loader ----
    auto load_stage = [&](int kt, int s) {
        const uint32_t sbase = SM_BUF + s * (NT * TILEB);
        const int kofs = kt * 32;
#pragma unroll
        for (int i = 0; i < NT * 2; i++) {
            int c   = tid + i * 256;      // 0 .. NT*512-1
            int t4  = c >> 9;             // tile id
            int rem = c & 511;
            int row = rem >> 2;
            int ch  = rem & 3;
            const __half* src;
            if constexpr (SPLIT == 1) {
                src = (t4 == 0) ? Ah + (size_t)(bm + row) * K + kofs + ch * 8
                                : Bh + (size_t)(bn + row) * K + kofs + ch * 8;
            } else {
                if (t4 == 0)      src = Ah + (size_t)(bm + row) * K + kofs + ch * 8;
                else if (t4 == 1) src = Al + (size_t)(bm + row) * K + kofs + ch * 8;
                else if (t4 == 2) src = Bh + (size_t)(bn + row) * K + kofs + ch * 8;
                else              src = Bl + (size_t)(bn + row) * K + kofs + ch * 8;
            }
            cp16(sbase + t4 * TILEB + row * RSB + ch * 16, src);
        }
        asm volatile("cp.async.commit_group;" ::: "memory");
    };

    // ---- prologue ----
#pragma unroll
    for (int p = 0; p < STAGES - 1; p++)
        if (p < nkt) load_stage(p, p);

    for (int kt = 0; kt < nkt; kt++) {
        const int nf = kt + STAGES - 1;
        if (nf < nkt) load_stage(nf, nf % STAGES);

        // wait until stage kt's group is complete
        int newer = ((nf < nkt ? nf : nkt - 1)) - kt;
        if (newer == 0) cp_wait<0>();
        else if (newer == 1) cp_wait<1>();
        else cp_wait<2>();
        __syncthreads();

        const uint32_t sbase  = SM_BUF + (kt % STAGES) * (NT * TILEB);
        const uint32_t aBase  = sbase;
        const uint32_t alBase = sbase + TILEB;
        const uint32_t bBase  = sbase + ((SPLIT == 3) ? 2 : 1) * TILEB;
        const uint32_t blBase = bBase + TILEB;

#pragma unroll
        for (int ks = 0; ks < 2; ks++) {
            uint32_t ah[4][4], al[4][4];
#pragma unroll
            for (int mt = 0; mt < 4; mt++) {
                uint32_t aoff = (uint32_t)(wm + mt * 16 + (lane & 15)) * RSB +
                                ks * 32 + ((lane >> 4) & 1) * 16;
                ldsm4a(ah[mt], aBase + aoff);
                if constexpr (SPLIT == 3) ldsm4a(al[mt], alBase + aoff);
            }
#pragma unroll
            for (int nt2 = 0; nt2 < 2; nt2++) {
                uint32_t boff = (uint32_t)(wn + nt2 * 16 + (lane & 7) +
                                           ((lane >> 4) & 1) * 8) * RSB +
                                ((lane >> 3) & 1) * 16 + ks * 32;
                uint32_t bh[4], bl[4];
                ldsm4a(bh, bBase + boff);
                if constexpr (SPLIT == 3) ldsm4a(bl, blBase + boff);
#pragma unroll
                for (int half = 0; half < 2; half++) {
                    const int j = nt2 * 2 + half;
#pragma unroll
                    for (int mt = 0; mt < 4; mt++) {
                        mma_f16(acc[mt][j], ah[mt], bh + half * 2);
                        if constexpr (SPLIT == 3) {
                            mma_f16(acc[mt][j], ah[mt], bl + half * 2);
                            mma_f16(acc[mt][j], al[mt], bh + half * 2);
                        }
                    }
                }
            }
        }
        __syncthreads();   // all warps done with this stage before it is refilled
    }

    // ---- epilogue ----
    const int g  = lane >> 2;
    const int tg = lane & 3;
#pragma unroll
    for (int nt = 0; nt < 4; nt++) {
        int col = bn + wn + nt * 8 + tg * 2;
        float b0 = (bias != nullptr) ? bias[col] : 0.f;
        float b1 = (bias != nullptr) ? bias[col + 1] : 0.f;
#pragma unroll
        for (int mt = 0; mt < 4; mt++) {
            int r0 = bm + wm + mt * 16 + g;
            float2 v0 = make_float2(acc[mt][nt][0] + b0, acc[mt][nt][1] + b1);
            float2 v1 = make_float2(acc[mt][nt][2] + b0, acc[mt][nt][3] + b1);
            *(float2*)(C + (size_t)r0 * N + col) = v0;
            *(float2*)(C + (size_t)(r0 + 8) * N + col) = v1;
        }
    }
}

// ---------------------------------------------------------------------------
// Windowed attention (fp32), outputs split-fp16 hi/lo for GEMM2.
// ---------------------------------------------------------------------------
__global__ __launch_bounds__(224) void attn_kernel(const float* __restrict__ qkv,
                                                   __half* __restrict__ ahi,
                                                   __half* __restrict__ alo) {
    __shared__ float ks[TJ][HD];
    __shared__ float vs[TJ][HD];

    const int bid = blockIdx.x;
    const int h   = bid % NHD;
    const int l   = (bid / NHD) % LWIN;
    const int b   = bid / (NHD * LWIN);
    const int wy  = l / NWIN;
    const int wx  = l % NWIN;
    const int t   = threadIdx.x;

    float q[HD];
    bool qvalid = false;
    int tok = 0;
    if (t < NW) {
        int ly = t / WIN, lx = t % WIN;
        int gy = wy * WIN + ly, gx = wx * WIN + lx;
        if (gy < Hh && gx < Wd) { qvalid = true; tok = gy * Wd + gx; }
    }
    if (qvalid) {
        const float4* qp = (const float4*)(qkv + ((size_t)b * NPOS + tok) * C3 + h * HD);
#pragma unroll
        for (int d4 = 0; d4 < HD / 4; d4++) {
            float4 v4 = qp[d4];
            q[d4 * 4 + 0] = v4.x; q[d4 * 4 + 1] = v4.y;
            q[d4 * 4 + 2] = v4.z; q[d4 * 4 + 3] = v4.w;
        }
    } else {
#pragma unroll
        for (int d = 0; d < HD; d++) q[d] = 0.f;
    }

    float acc[HD];
#pragma unroll
    for (int d = 0; d < HD; d++) acc[d] = 0.f;
    float lsum = 0.f;

    for (int jt = 0; jt < NW; jt += TJ) {
        __syncthreads();
#pragma unroll
        for (int s = 0; s < 2; s++) {
            int idx = t + s * 224;
            int jj  = idx >> 4;
            int c4  = (idx & 15) * 4;
            int j   = jt + jj;
            int jy = j / WIN, jx = j % WIN;
            int gy = wy * WIN + jy, gx = wx * WIN + jx;
            float4 kv = make_float4(0.f, 0.f, 0.f, 0.f);
            float4 vv = make_float4(0.f, 0.f, 0.f, 0.f);
            if (gy < Hh && gx < Wd) {
                const float* base = qkv + ((size_t)b * NPOS + gy * Wd + gx) * C3 + h * HD + c4;
                kv = *(const float4*)(base + Cc);
                vv = *(const float4*)(base + 2 * Cc);
            }
            *(float4*)&ks[jj][c4] = kv;
            *(float4*)&vs[jj][c4] = vv;
        }
        __syncthreads();

        for (int jj = 0; jj < TJ; jj++) {
            float s0 = 0.f, s1 = 0.f, s2 = 0.f, s3 = 0.f;
#pragma unroll
            for (int d = 0; d < HD; d += 4) {
                s0 += q[d + 0] * ks[jj][d + 0];
                s1 += q[d + 1] * ks[jj][d + 1];
                s2 += q[d + 2] * ks[jj][d + 2];
                s3 += q[d + 3] * ks[jj][d + 3];
            }
            float p = __expf(((s0 + s1) + (s2 + s3)) * 0.125f);
            lsum += p;
#pragma unroll
            for (int d = 0; d < HD; d++) acc[d] += p * vs[jj][d];
        }
    }

    if (qvalid) {
        float inv = 1.0f / lsum;
        size_t off = ((size_t)b * NPOS + tok) * Cc + h * HD;
#pragma unroll
        for (int d = 0; d < HD; d += 2) {
            __half h0, l0, h1, l1;
            split2h(acc[d + 0] * inv, h0, l0);
            split2h(acc[d + 1] * inv, h1, l1);
            *(__half2*)(ahi + off + d) = __halves2half2(h0, h1);
            *(__half2*)(alo + off + d) = __halves2half2(l0, l1);
        }
    }
}

// ---------------------------------------------------------------------------
extern "C" void kernel_launch(void* const* d_in, const int* in_sizes, int n_in,
                              void* d_out, int out_size) {
    const float* x     = (const float*)d_in[0];
    const float* Wqkv  = (const float*)d_in[1];
    const float* Wproj = (const float*)d_in[2];
    const float* bproj = (const float*)d_in[3];
    float* out = (float*)d_out;

    float* qkv;
    __half *xh, *ahi, *alo, *wq, *wph, *wpl;
    cudaGetSymbolAddress((void**)&qkv, g_qkv);
    cudaGetSymbolAddress((void**)&xh,  g_xh);
    cudaGetSymbolAddress((void**)&ahi, g_ahi);
    cudaGetSymbolAddress((void**)&alo, g_alo);
    cudaGetSymbolAddress((void**)&wq,  g_wq);
    cudaGetSymbolAddress((void**)&wph, g_wph);
    cudaGetSymbolAddress((void**)&wpl, g_wpl);

    const int SM1 = 3 * 2 * TILEB;   // SPLIT=1, STAGES=3 -> 110592 B
    const int SM2 = 2 * 4 * TILEB;   // SPLIT=3, STAGES=2 -> 147456 B
    cudaFuncSetAttribute(gemm_hmma<1, 3>, cudaFuncAttributeMaxDynamicSharedMemorySize, SM1);
    cudaFuncSetAttribute(gemm_hmma<3, 2>, cudaFuncAttributeMaxDynamicSharedMemorySize, SM2);

    // Prep
    {
        int n4 = Mrows * Cc / 4;
        conv_half<<<(n4 + 255) / 256, 256>>>(x, xh, n4);
        dim3 tb(32, 8);
        transpose_half<<<dim3(C3 / 32, Cc / 32), tb>>>(Wqkv, wq, nullptr, Cc, C3);
        transpose_half<<<dim3(Cc / 32, Cc / 32), tb>>>(Wproj, wph, wpl, Cc, Cc);
    }

    // GEMM1: qkv = x @ Wqkv  (single-product fp16)
    gemm_hmma<1, 3><<<dim3(C3 / 128, Mrows / 128), 256, SM1>>>(
        xh, nullptr, wq, nullptr, nullptr, qkv, Mrows, C3, Cc);

    // Attention -> split-fp16 output
    attn_kernel<<<Bn * LWIN * NHD, 224>>>(qkv, ahi, alo);

    // GEMM2: out = att @ Wproj + bias  (3-product fp16-split)
    gemm_hmma<3, 2><<<dim3(Cc / 128, Mrows / 128), 256, SM2>>>(
        ahi, alo, wph, wpl, bproj, out, Mrows, Cc, Cc);
}

// round 14
// speedup vs baseline: 2.7422x; 1.1711x over previous
#include <cuda_runtime.h>
#include <cuda_fp16.h>
#include <cstdint>

// Problem constants
#define Bn   8
#define Hh   80
#define Wd   80
#define Cc   768
#define C3   2304
#define NPOS 6400
#define WIN  14
#define NWIN 6
#define LWIN 36
#define NW   196
#define NHD  12
#define HD   64
#define Mrows (Bn * NPOS)   // 51200

// ---------------------------------------------------------------------------
// Scratch (no cudaMalloc allowed)
// ---------------------------------------------------------------------------
__device__ float  g_qkv[(size_t)Mrows * C3];     // 472 MB fp32
__device__ __half g_xh [(size_t)Mrows * Cc];     // x in fp16
__device__ __half g_ahi[(size_t)Mrows * Cc];     // attention out hi
__device__ __half g_alo[(size_t)Mrows * Cc];     // attention out lo
__device__ __half g_wq [(size_t)C3 * Cc];        // Wqkv^T fp16 [2304,768]
__device__ __half g_wph[(size_t)Cc * Cc];        // Wproj^T hi  [768,768]
__device__ __half g_wpl[(size_t)Cc * Cc];        // Wproj^T lo

// ---------------------------------------------------------------------------
// Helpers
// ---------------------------------------------------------------------------
__device__ __forceinline__ uint32_t smem_u32(const void* p) {
    uint32_t a;
    asm("{ .reg .u64 t; cvta.to.shared.u64 t, %1; cvt.u32.u64 %0, t; }" : "=r"(a) : "l"(p));
    return a;
}
__device__ __forceinline__ void ldsm4a(uint32_t* r, uint32_t addr) {
    asm volatile("ldmatrix.sync.aligned.m8n8.x4.shared.b16 {%0,%1,%2,%3}, [%4];"
                 : "=r"(r[0]), "=r"(r[1]), "=r"(r[2]), "=r"(r[3]) : "r"(addr));
}
__device__ __forceinline__ void ldsm4t(uint32_t* r, uint32_t addr) {
    asm volatile("ldmatrix.sync.aligned.m8n8.x4.trans.shared.b16 {%0,%1,%2,%3}, [%4];"
                 : "=r"(r[0]), "=r"(r[1]), "=r"(r[2]), "=r"(r[3]) : "r"(addr));
}
__device__ __forceinline__ void mma_f16(float* c, const uint32_t* a, const uint32_t* b) {
    asm volatile("mma.sync.aligned.m16n8k16.row.col.f32.f16.f16.f32 "
                 "{%0,%1,%2,%3}, {%4,%5,%6,%7}, {%8,%9}, {%0,%1,%2,%3};"
                 : "+f"(c[0]), "+f"(c[1]), "+f"(c[2]), "+f"(c[3])
                 : "r"(a[0]), "r"(a[1]), "r"(a[2]), "r"(a[3]),
                   "r"(b[0]), "r"(b[1]));
}
__device__ __forceinline__ void cp16(uint32_t dst, const void* src) {
    asm volatile("cp.async.cg.shared.global [%0], [%1], 16;" :: "r"(dst), "l"(src));
}
template <int N>
__device__ __forceinline__ void cp_wait() {
    asm volatile("cp.async.wait_group %0;" :: "n"(N) : "memory");
}
__device__ __forceinline__ void split2h(float v, __half& hi, __half& lo) {
    hi = __float2half(v);
    lo = __float2half(v - __half2float(hi));
}

// ---------------------------------------------------------------------------
// Prep kernels
// ---------------------------------------------------------------------------
__global__ void conv_half(const float* __restrict__ in, __half* __restrict__ out, int n4) {
    int i = blockIdx.x * blockDim.x + threadIdx.x;
    if (i >= n4) return;
    float4 v = ((const float4*)in)[i];
    ((__half2*)out)[i * 2 + 0] = __floats2half2_rn(v.x, v.y);
    ((__half2*)out)[i * 2 + 1] = __floats2half2_rn(v.z, v.w);
}

// W [K,N] fp32 row-major -> T [N,K] fp16 row-major (optional lo)
__global__ void transpose_half(const float* __restrict__ W, __half* __restrict__ Th,
                               __half* __restrict__ Tl, int K, int N) {
    __shared__ float t[32][33];
    int n0 = blockIdx.x * 32, k0 = blockIdx.y * 32;
    int tx = threadIdx.x, ty = threadIdx.y;   // 32 x 8
#pragma unroll
    for (int i = 0; i < 32; i += 8)
        t[ty + i][tx] = W[(size_t)(k0 + ty + i) * N + n0 + tx];
    __syncthreads();
#pragma unroll
    for (int i = 0; i < 32; i += 8) {
        float v = t[tx][ty + i];
        __half hi, lo;
        split2h(v, hi, lo);
        Th[(size_t)(n0 + ty + i) * K + k0 + tx] = hi;
        if (Tl != nullptr) Tl[(size_t)(n0 + ty + i) * K + k0 + tx] = lo;
    }
}

// ---------------------------------------------------------------------------
// fp16 HMMA GEMM (unchanged from R12): C = A @ Bt^T (+bias), fp32 accum.
// ---------------------------------------------------------------------------
#define RSB   144                    // bytes per 32-halfword k-row
#define TILEB (128 * RSB)            // 18432 B

template <int SPLIT, int STAGES>
__global__ __launch_bounds__(256)
void gemm_hmma(const __half* __restrict__ Ah, const __half* __restrict__ Al,
               const __half* __restrict__ Bh, const __half* __restrict__ Bl,
               const float* __restrict__ bias, float* __restrict__ C,
               int M, int N, int K) {
    constexpr int NT = (SPLIT == 3) ? 4 : 2;     // tiles per stage
    extern __shared__ char smem[];
    const uint32_t SM_BUF = smem_u32(smem);

    const int tid  = threadIdx.x;
    const int warp = tid >> 5;
    const int lane = tid & 31;
    const int wm   = (warp >> 2) * 64;   // 0 / 64
    const int wn   = (warp & 3) * 32;    // 0,32,64,96
    const int bm   = blockIdx.y * 128;
    const int bn   = blockIdx.x * 128;
    const int nkt  = K / 32;

    float acc[4][4][4];
#pragma unroll
    for (int i = 0; i < 4; i++)
#pragma unroll
        for (int j = 0; j < 4; j++)
#pragma unroll
            for (int e = 0; e < 4; e++) acc[i][j][e] = 0.f;

    auto load_stage = [&](int kt, int s) {
        const uint32_t sbase = SM_BUF + s * (NT * TILEB);
        const int kofs = kt * 32;
#pragma unroll
        for (int i = 0; i < NT * 2; i++) {
            int c   = tid + i * 256;
            int t4  = c >> 9;
            int rem = c & 511;
            int row = rem >> 2;
            int ch  = rem & 3;
            const __half* src;
            if constexpr (SPLIT == 1) {
                src = (t4 == 0) ? Ah + (size_t)(bm + row) * K + kofs + ch * 8
                                : Bh + (size_t)(bn + row) * K + kofs + ch * 8;
            } else {
                if (t4 == 0)      src = Ah + (size_t)(bm + row) * K + kofs + ch * 8;
                else if (t4 == 1) src = Al + (size_t)(bm + row) * K + kofs + ch * 8;
                else if (t4 == 2) src = Bh + (size_t)(bn + row) * K + kofs + ch * 8;
                else              src = Bl + (size_t)(bn + row) * K + kofs + ch * 8;
            }
            cp16(sbase + t4 * TILEB + row * RSB + ch * 16, src);
        }
        asm volatile("cp.async.commit_group;" ::: "memory");
    };

#pragma unroll
    for (int p = 0; p < STAGES - 1; p++)
        if (p < nkt) load_stage(p, p);

    for (int kt = 0; kt < nkt; kt++) {
        const int nf = kt + STAGES - 1;
        if (nf < nkt) load_stage(nf, nf % STAGES);

        int newer = ((nf < nkt ? nf : nkt - 1)) - kt;
        if (newer == 0) cp_wait<0>();
        else if (newer == 1) cp_wait<1>();
        else cp_wait<2>();
        __syncthreads();

        const uint32_t sbase  = SM_BUF + (kt % STAGES) * (NT * TILEB);
        const uint32_t aBase  = sbase;
        const uint32_t alBase = sbase + TILEB;
        const uint32_t bBase  = sbase + ((SPLIT == 3) ? 2 : 1) * TILEB;
        const uint32_t blBase = bBase + TILEB;

#pragma unroll
        for (int ks = 0; ks < 2; ks++) {
            uint32_t ah[4][4], al[4][4];
#pragma unroll
            for (int mt = 0; mt < 4; mt++) {
                uint32_t aoff = (uint32_t)(wm + mt * 16 + (lane & 15)) * RSB +
                                ks * 32 + ((lane >> 4) & 1) * 16;
                ldsm4a(ah[mt], aBase + aoff);
                if constexpr (SPLIT == 3) ldsm4a(al[mt], alBase + aoff);
            }
#pragma unroll
            for (int nt2 = 0; nt2 < 2; nt2++) {
                uint32_t boff = (uint32_t)(wn + nt2 * 16 + (lane & 7) +
                                           ((lane >> 4) & 1) * 8) * RSB +
                                ((lane >> 3) & 1) * 16 + ks * 32;
                uint32_t bh[4], bl[4];
                ldsm4a(bh, bBase + boff);
                if constexpr (SPLIT == 3) ldsm4a(bl, blBase + boff);
#pragma unroll
                for (int half = 0; half < 2; half++) {
                    const int j = nt2 * 2 + half;
#pragma unroll
                    for (int mt = 0; mt < 4; mt++) {
                        mma_f16(acc[mt][j], ah[mt], bh + half * 2);
                        if constexpr (SPLIT == 3) {
                            mma_f16(acc[mt][j], ah[mt], bl + half * 2);
                            mma_f16(acc[mt][j], al[mt], bh + half * 2);
                        }
                    }
                }
            }
        }
        __syncthreads();
    }

    const int g  = lane >> 2;
    const int tg = lane & 3;
#pragma unroll
    for (int nt = 0; nt < 4; nt++) {
        int col = bn + wn + nt * 8 + tg * 2;
        float b0 = (bias != nullptr) ? bias[col] : 0.f;
        float b1 = (bias != nullptr) ? bias[col + 1] : 0.f;
#pragma unroll
        for (int mt = 0; mt < 4; mt++) {
            int r0 = bm + wm + mt * 16 + g;
            float2 v0 = make_float2(acc[mt][nt][0] + b0, acc[mt][nt][1] + b1);
            float2 v1 = make_float2(acc[mt][nt][2] + b0, acc[mt][nt][3] + b1);
            *(float2*)(C + (size_t)r0 * N + col) = v0;
            *(float2*)(C + (size_t)(r0 + 8) * N + col) = v1;
        }
    }
}

// ---------------------------------------------------------------------------
// Tensor-core windowed attention. One CTA per (b, window, head), 7 warps.
// Rows padded 196->224 (warp w owns rows 32w..32w+31). K-cols processed in
// 7 chunks of 32; cols >=196 masked to p=0 after exp. Scale folded into Q.
// Smem: Q/K/V fp16 [224][72] (144B row stride, conflict-free ldmatrix).
// Output: split-fp16 hi/lo for GEMM2. No max-subtraction (logits ~N(0,0.3)).
// ---------------------------------------------------------------------------
#define ARS 144                      // attn smem row stride bytes (72 halfs)
#define ATILE (224 * ARS)            // 32256 B per tensor
#define ASMEM (3 * ATILE)            // 96768 B

__global__ __launch_bounds__(224, 1)
void attn_tc(const float* __restrict__ qkv,
             __half* __restrict__ ahi, __half* __restrict__ alo) {
    extern __shared__ char smraw[];
    __half* Qs = (__half*)smraw;
    __half* Ks = Qs + 224 * 72;
    __half* Vs = Ks + 224 * 72;
    const uint32_t SQ = smem_u32(smraw);
    const uint32_t SK = SQ + ATILE;
    const uint32_t SV = SK + ATILE;

    const int bid = blockIdx.x;
    const int h   = bid % NHD;
    const int l   = (bid / NHD) % LWIN;
    const int b   = bid / (NHD * LWIN);
    const int wy  = l / NWIN;
    const int wx  = l % NWIN;
    const int t   = threadIdx.x;
    const int warp = t >> 5;
    const int lane = t & 31;
    const int g    = lane >> 2;
    const int tg   = lane & 3;

    // ---- load Q,K,V rows (fp32 -> fp16), zero pad rows ----
    {
        const int r = t;   // 0..223, one row per thread
        bool valid = false;
        int tok = 0;
        if (r < NW) {
            int ly = r / WIN, lx = r % WIN;
            int gy = wy * WIN + ly, gx = wx * WIN + lx;
            if (gy < Hh && gx < Wd) { valid = true; tok = gy * Wd + gx; }
        }
        __half2* qr = (__half2*)(Qs + r * 72);
        __half2* kr = (__half2*)(Ks + r * 72);
        __half2* vr = (__half2*)(Vs + r * 72);
        if (valid) {
            const float4* p = (const float4*)(qkv + ((size_t)b * NPOS + tok) * C3 + h * HD);
#pragma unroll
            for (int i = 0; i < 16; i++) {
                float4 vq = p[i];
                qr[i * 2 + 0] = __floats2half2_rn(vq.x * 0.125f, vq.y * 0.125f);
                qr[i * 2 + 1] = __floats2half2_rn(vq.z * 0.125f, vq.w * 0.125f);
                float4 vk = p[i + 192];            // +Cc floats
                kr[i * 2 + 0] = __floats2half2_rn(vk.x, vk.y);
                kr[i * 2 + 1] = __floats2half2_rn(vk.z, vk.w);
                float4 vv = p[i + 384];            // +2Cc floats
                vr[i * 2 + 0] = __floats2half2_rn(vv.x, vv.y);
                vr[i * 2 + 1] = __floats2half2_rn(vv.z, vv.w);
            }
        } else {
            const __half2 z = __floats2half2_rn(0.f, 0.f);
#pragma unroll
            for (int i = 0; i < 32; i++) { qr[i] = z; kr[i] = z; vr[i] = z; }
        }
    }
    __syncthreads();

    const int wr = warp * 32;

    // Q fragments for this warp's 32 rows (held all kernel)
    uint32_t qf[2][4][4];
#pragma unroll
    for (int mt = 0; mt < 2; mt++)
#pragma unroll
        for (int kk = 0; kk < 4; kk++) {
            uint32_t addr = SQ + (uint32_t)(wr + mt * 16 + (lane & 15)) * ARS +
                            kk * 32 + ((lane >> 4) & 1) * 16;
            ldsm4a(qf[mt][kk], addr);
        }

    float oacc[2][8][4];
#pragma unroll
    for (int mt = 0; mt < 2; mt++)
#pragma unroll
        for (int nt = 0; nt < 8; nt++)
#pragma unroll
            for (int e = 0; e < 4; e++) oacc[mt][nt][e] = 0.f;
    float rs[2][2] = {{0.f, 0.f}, {0.f, 0.f}};

#pragma unroll 1
    for (int c = 0; c < 7; c++) {
        const int kb = c * 32;

        // ---- S = Q @ K^T (chunk of 32 key-cols) ----
        float sa[2][4][4];
#pragma unroll
        for (int mt = 0; mt < 2; mt++)
#pragma unroll
            for (int nt = 0; nt < 4; nt++)
#pragma unroll
                for (int e = 0; e < 4; e++) sa[mt][nt][e] = 0.f;

#pragma unroll
        for (int kk = 0; kk < 4; kk++) {
#pragma unroll
            for (int nn = 0; nn < 2; nn++) {
                uint32_t kf[4];
                uint32_t addr = SK + (uint32_t)(kb + nn * 16 + (lane & 7) +
                                                ((lane >> 4) & 1) * 8) * ARS +
                                ((lane >> 3) & 1) * 16 + kk * 32;
                ldsm4a(kf, addr);
#pragma unroll
                for (int mt = 0; mt < 2; mt++) {
                    mma_f16(sa[mt][2 * nn + 0], qf[mt][kk], kf + 0);
                    mma_f16(sa[mt][2 * nn + 1], qf[mt][kk], kf + 2);
                }
            }
        }

        // ---- exp + mask + rowsum ----
#pragma unroll
        for (int mt = 0; mt < 2; mt++)
#pragma unroll
            for (int nt = 0; nt < 4; nt++) {
#pragma unroll
                for (int e = 0; e < 4; e++) {
                    float p = __expf(sa[mt][nt][e]);
                    if (c == 6) {
                        int col = kb + nt * 8 + 2 * tg + (e & 1);
                        if (col >= NW) p = 0.f;
                    }
                    sa[mt][nt][e] = p;
                }
                rs[mt][0] += sa[mt][nt][0] + sa[mt][nt][1];
                rs[mt][1] += sa[mt][nt][2] + sa[mt][nt][3];
            }

        // ---- O += P @ V ----
#pragma unroll
        for (int j = 0; j < 2; j++) {          // k16 groups within chunk
            uint32_t ap[2][4];
#pragma unroll
            for (int mt = 0; mt < 2; mt++) {
                __half2 a0 = __floats2half2_rn(sa[mt][2 * j][0], sa[mt][2 * j][1]);
                __half2 a1 = __floats2half2_rn(sa[mt][2 * j][2], sa[mt][2 * j][3]);
                __half2 a2 = __floats2half2_rn(sa[mt][2 * j + 1][0], sa[mt][2 * j + 1][1]);
                __half2 a3 = __floats2half2_rn(sa[mt][2 * j + 1][2], sa[mt][2 * j + 1][3]);
                ap[mt][0] = *(uint32_t*)&a0;
                ap[mt][1] = *(uint32_t*)&a1;
                ap[mt][2] = *(uint32_t*)&a2;
                ap[mt][3] = *(uint32_t*)&a3;
            }
#pragma unroll
            for (int nn = 0; nn < 4; nn++) {   // hd n16 groups
                uint32_t vf[4];
                uint32_t addr = SV + (uint32_t)(kb + j * 16 + (lane & 15)) * ARS +
                                nn * 32 + ((lane >> 4) & 1) * 16;
                ldsm4t(vf, addr);
#pragma unroll
                for (int mt = 0; mt < 2; mt++) {
                    mma_f16(oacc[mt][2 * nn + 0], ap[mt], vf + 0);
                    mma_f16(oacc[mt][2 * nn + 1], ap[mt], vf + 2);
                }
            }
        }
    }

    // ---- rowsum reduce across quad (tg bits = lane bits 0,1) ----
#pragma unroll
    for (int mt = 0; mt < 2; mt++)
#pragma unroll
        for (int e = 0; e < 2; e++) {
            float v = rs[mt][e];
            v += __shfl_xor_sync(0xffffffff, v, 1);
            v += __shfl_xor_sync(0xffffffff, v, 2);
            rs[mt][e] = 1.f / v;
        }

    // ---- epilogue: normalize, split-fp16, store ----
#pragma unroll
    for (int mt = 0; mt < 2; mt++) {
#pragma unroll
        for (int e = 0; e < 2; e++) {          // row g (e=0) / g+8 (e=1)
            int r = wr + mt * 16 + g + e * 8;
            if (r >= NW) continue;
            int ly = r / WIN, lx = r % WIN;
            int gy = wy * WIN + ly, gx = wx * WIN + lx;
            if (gy >= Hh || gx >= Wd) continue;
            size_t off = ((size_t)b * NPOS + gy * Wd + gx) * Cc + h * HD + 2 * tg;
            float inv = rs[mt][e];
#pragma unroll
            for (int nt = 0; nt < 8; nt++) {
                float v0 = oacc[mt][nt][e * 2 + 0] * inv;
                float v1 = oacc[mt][nt][e * 2 + 1] * inv;
                __half h0, l0, h1, l1;
                split2h(v0, h0, l0);
                split2h(v1, h1, l1);
                *(__half2*)(ahi + off + nt * 8) = __halves2half2(h0, h1);
                *(__half2*)(alo + off + nt * 8) = __halves2half2(l0, l1);
            }
        }
    }
}

// ---------------------------------------------------------------------------
extern "C" void kernel_launch(void* const* d_in, const int* in_sizes, int n_in,
                              void* d_out, int out_size) {
    const float* x     = (const float*)d_in[0];
    const float* Wqkv  = (const float*)d_in[1];
    const float* Wproj = (const float*)d_in[2];
    const float* bproj = (const float*)d_in[3];
    float* out = (float*)d_out;

    float* qkv;
    __half *xh, *ahi, *alo, *wq, *wph, *wpl;
    cudaGetSymbolAddress((void**)&qkv, g_qkv);
    cudaGetSymbolAddress((void**)&xh,  g_xh);
    cudaGetSymbolAddress((void**)&ahi, g_ahi);
    cudaGetSymbolAddress((void**)&alo, g_alo);
    cudaGetSymbolAddress((void**)&wq,  g_wq);
    cudaGetSymbolAddress((void**)&wph, g_wph);
    cudaGetSymbolAddress((void**)&wpl, g_wpl);

    const int SM1 = 3 * 2 * TILEB;   // 110592 B
    const int SM2 = 2 * 4 * TILEB;   // 147456 B
    cudaFuncSetAttribute(gemm_hmma<1, 3>, cudaFuncAttributeMaxDynamicSharedMemorySize, SM1);
    cudaFuncSetAttribute(gemm_hmma<3, 2>, cudaFuncAttributeMaxDynamicSharedMemorySize, SM2);
    cudaFuncSetAttribute(attn_tc, cudaFuncAttributeMaxDynamicSharedMemorySize, ASMEM);

    // Prep
    {
        int n4 = Mrows * Cc / 4;
        conv_half<<<(n4 + 255) / 256, 256>>>(x, xh, n4);
        dim3 tb(32, 8);
        transpose_half<<<dim3(C3 / 32, Cc / 32), tb>>>(Wqkv, wq, nullptr, Cc, C3);
        transpose_half<<<dim3(Cc / 32, Cc / 32), tb>>>(Wproj, wph, wpl, Cc, Cc);
    }

    // GEMM1: qkv = x @ Wqkv  (single-product fp16)
    gemm_hmma<1, 3><<<dim3(C3 / 128, Mrows / 128), 256, SM1>>>(
        xh, nullptr, wq, nullptr, nullptr, qkv, Mrows, C3, Cc);

    // Tensor-core attention -> split-fp16 output
    attn_tc<<<Bn * LWIN * NHD, 224, ASMEM>>>(qkv, ahi, alo);

    // GEMM2: out = att @ Wproj + bias  (3-product fp16-split)
    gemm_hmma<3, 2><<<dim3(Cc / 128, Mrows / 128), 256, SM2>>>(
        ahi, alo, wph, wpl, bproj, out, Mrows, Cc, Cc);
}

// round 16
// speedup vs baseline: 5.8251x; 2.1243x over previous
#include <cuda_runtime.h>
#include <cuda_fp16.h>
#include <cstdint>

// Problem constants
#define Bn   8
#define Hh   80
#define Wd   80
#define Cc   768
#define C3   2304
#define NPOS 6400
#define WIN  14
#define NWIN 6
#define LWIN 36
#define NW   196
#define NHD  12
#define HD   64
#define Mrows (Bn * NPOS)   // 51200

// ---------------------------------------------------------------------------
// Scratch (no cudaMalloc allowed)
// ---------------------------------------------------------------------------
__device__ __half g_qkv[(size_t)Mrows * C3];     // 236 MB fp16 (q pre-scaled)
__device__ __half g_xh [(size_t)Mrows * Cc];     // x in fp16
__device__ __half g_att[(size_t)Mrows * Cc];     // attention out fp16
__device__ __half g_wq [(size_t)C3 * Cc];        // Wqkv^T fp16 [2304,768]
__device__ __half g_wp [(size_t)Cc * Cc];        // Wproj^T fp16 [768,768]

// ---------------------------------------------------------------------------
// Helpers
// ---------------------------------------------------------------------------
__device__ __forceinline__ uint32_t smem_u32(const void* p) {
    uint32_t a;
    asm("{ .reg .u64 t; cvta.to.shared.u64 t, %1; cvt.u32.u64 %0, t; }" : "=r"(a) : "l"(p));
    return a;
}
__device__ __forceinline__ void ldsm4a(uint32_t* r, uint32_t addr) {
    asm volatile("ldmatrix.sync.aligned.m8n8.x4.shared.b16 {%0,%1,%2,%3}, [%4];"
                 : "=r"(r[0]), "=r"(r[1]), "=r"(r[2]), "=r"(r[3]) : "r"(addr));
}
__device__ __forceinline__ void ldsm4t(uint32_t* r, uint32_t addr) {
    asm volatile("ldmatrix.sync.aligned.m8n8.x4.trans.shared.b16 {%0,%1,%2,%3}, [%4];"
                 : "=r"(r[0]), "=r"(r[1]), "=r"(r[2]), "=r"(r[3]) : "r"(addr));
}
__device__ __forceinline__ void mma_f16(float* c, const uint32_t* a, const uint32_t* b) {
    asm volatile("mma.sync.aligned.m16n8k16.row.col.f32.f16.f16.f32 "
                 "{%0,%1,%2,%3}, {%4,%5,%6,%7}, {%8,%9}, {%0,%1,%2,%3};"
                 : "+f"(c[0]), "+f"(c[1]), "+f"(c[2]), "+f"(c[3])
                 : "r"(a[0]), "r"(a[1]), "r"(a[2]), "r"(a[3]),
                   "r"(b[0]), "r"(b[1]));
}
__device__ __forceinline__ void cp16(uint32_t dst, const void* src) {
    asm volatile("cp.async.cg.shared.global [%0], [%1], 16;" :: "r"(dst), "l"(src));
}
template <int N>
__device__ __forceinline__ void cp_wait() {
    asm volatile("cp.async.wait_group %0;" :: "n"(N) : "memory");
}

// ---------------------------------------------------------------------------
// Prep kernels
// ---------------------------------------------------------------------------
__global__ void conv_half(const float* __restrict__ in, __half* __restrict__ out, int n4) {
    int i = blockIdx.x * blockDim.x + threadIdx.x;
    if (i >= n4) return;
    float4 v = ((const float4*)in)[i];
    ((__half2*)out)[i * 2 + 0] = __floats2half2_rn(v.x, v.y);
    ((__half2*)out)[i * 2 + 1] = __floats2half2_rn(v.z, v.w);
}

// W [K,N] fp32 row-major -> T [N,K] fp16 row-major
__global__ void transpose_half(const float* __restrict__ W, __half* __restrict__ Th,
                               int K, int N) {
    __shared__ float t[32][33];
    int n0 = blockIdx.x * 32, k0 = blockIdx.y * 32;
    int tx = threadIdx.x, ty = threadIdx.y;   // 32 x 8
#pragma unroll
    for (int i = 0; i < 32; i += 8)
        t[ty + i][tx] = W[(size_t)(k0 + ty + i) * N + n0 + tx];
    __syncthreads();
#pragma unroll
    for (int i = 0; i < 32; i += 8)
        Th[(size_t)(n0 + ty + i) * K + k0 + tx] = __float2half(t[tx][ty + i]);
}

// ---------------------------------------------------------------------------
// fp16 HMMA GEMM: C[M,N] = A[M,K] @ Bt[N,K]^T (+bias), fp32 accum.
// CTA tile 128x128x32, 8 warps (2x4, warp tile 64x32), 2-stage cp.async.
// OutT=half: store fp16, scaling cols < qcols by qs (q pre-scale for attn).
// OutT=float: fp32 store + bias. Smem 73.7KB -> 2 CTAs/SM.
// ---------------------------------------------------------------------------
#define RSB   144                    // bytes per 32-halfword k-row
#define TILEB (128 * RSB)            // 18432 B
#define GSM   (2 * 2 * TILEB)        // 73728 B

template <typename OutT>
__global__ __launch_bounds__(256)
void gemm_hmma(const __half* __restrict__ Ah, const __half* __restrict__ Bh,
               const float* __restrict__ bias, OutT* __restrict__ C,
               int M, int N, int K, float qs, int qcols) {
    extern __shared__ char smem[];
    const uint32_t SM_BUF = smem_u32(smem);

    const int tid  = threadIdx.x;
    const int warp = tid >> 5;
    const int lane = tid & 31;
    const int wm   = (warp >> 2) * 64;   // 0 / 64
    const int wn   = (warp & 3) * 32;    // 0,32,64,96
    const int bm   = blockIdx.y * 128;
    const int bn   = blockIdx.x * 128;
    const int nkt  = K / 32;

    float acc[4][4][4];
#pragma unroll
    for (int i = 0; i < 4; i++)
#pragma unroll
        for (int j = 0; j < 4; j++)
#pragma unroll
            for (int e = 0; e < 4; e++) acc[i][j][e] = 0.f;

    auto load_stage = [&](int kt, int s) {
        const uint32_t sbase = SM_BUF + s * (2 * TILEB);
        const int kofs = kt * 32;
#pragma unroll
        for (int i = 0; i < 4; i++) {
            int c   = tid + i * 256;      // 0..1023
            int t4  = c >> 9;             // 0:A 1:B
            int rem = c & 511;
            int row = rem >> 2;
            int ch  = rem & 3;
            const __half* src = (t4 == 0)
                ? Ah + (size_t)(bm + row) * K + kofs + ch * 8
                : Bh + (size_t)(bn + row) * K + kofs + ch * 8;
            cp16(sbase + t4 * TILEB + row * RSB + ch * 16, src);
        }
        asm volatile("cp.async.commit_group;" ::: "memory");
    };

    load_stage(0, 0);

    for (int kt = 0; kt < nkt; kt++) {
        const int nf = kt + 1;
        if (nf < nkt) load_stage(nf, nf & 1);
        if (nf < nkt) cp_wait<1>();
        else          cp_wait<0>();
        __syncthreads();

        const uint32_t sbase = SM_BUF + (kt & 1) * (2 * TILEB);
        const uint32_t aBase = sbase;
        const uint32_t bBase = sbase + TILEB;

#pragma unroll
        for (int ks = 0; ks < 2; ks++) {
            uint32_t ah[4][4];
#pragma unroll
            for (int mt = 0; mt < 4; mt++) {
                uint32_t aoff = (uint32_t)(wm + mt * 16 + (lane & 15)) * RSB +
                                ks * 32 + ((lane >> 4) & 1) * 16;
                ldsm4a(ah[mt], aBase + aoff);
            }
#pragma unroll
            for (int nt2 = 0; nt2 < 2; nt2++) {
                uint32_t boff = (uint32_t)(wn + nt2 * 16 + (lane & 7) +
                                           ((lane >> 4) & 1) * 8) * RSB +
                                ((lane >> 3) & 1) * 16 + ks * 32;
                uint32_t bh[4];
                ldsm4a(bh, bBase + boff);
#pragma unroll
                for (int half = 0; half < 2; half++) {
                    const int j = nt2 * 2 + half;
#pragma unroll
                    for (int mt = 0; mt < 4; mt++)
                        mma_f16(acc[mt][j], ah[mt], bh + half * 2);
                }
            }
        }
        __syncthreads();
    }

    // ---- epilogue ----
    const int g  = lane >> 2;
    const int tg = lane & 3;
#pragma unroll
    for (int nt = 0; nt < 4; nt++) {
        int col = bn + wn + nt * 8 + tg * 2;
        float sc = (col < qcols) ? qs : 1.f;   // both pair cols in same region
        float b0 = (bias != nullptr) ? bias[col] : 0.f;
        float b1 = (bias != nullptr) ? bias[col + 1] : 0.f;
#pragma unroll
        for (int mt = 0; mt < 4; mt++) {
            int r0 = bm + wm + mt * 16 + g;
            if constexpr (sizeof(OutT) == 2) {
                __half2 v0 = __floats2half2_rn(acc[mt][nt][0] * sc, acc[mt][nt][1] * sc);
                __half2 v1 = __floats2half2_rn(acc[mt][nt][2] * sc, acc[mt][nt][3] * sc);
                *(__half2*)((__half*)C + (size_t)r0 * N + col) = v0;
                *(__half2*)((__half*)C + (size_t)(r0 + 8) * N + col) = v1;
            } else {
                float2 v0 = make_float2(acc[mt][nt][0] + b0, acc[mt][nt][1] + b1);
                float2 v1 = make_float2(acc[mt][nt][2] + b0, acc[mt][nt][3] + b1);
                *(float2*)((float*)C + (size_t)r0 * N + col) = v0;
                *(float2*)((float*)C + (size_t)(r0 + 8) * N + col) = v1;
            }
        }
    }
}

// ---------------------------------------------------------------------------
// Tensor-core windowed attention. One CTA per (b, window, head), 7 warps.
// qkv is fp16 with q pre-scaled; Q/K/V staged via cp.async (128B/row).
// Rows padded 196->224; key cols >=196 masked to p=0 after exp.
// Output: fp16 normalized attention rows for GEMM2.
// ---------------------------------------------------------------------------
#define ARS 144                      // attn smem row stride bytes (72 halfs)
#define ATILE (224 * ARS)            // 32256 B per tensor
#define ASMEM (3 * ATILE)            // 96768 B

__global__ __launch_bounds__(224, 1)
void attn_tc(const __half* __restrict__ qkv, __half* __restrict__ att) {
    extern __shared__ char smraw[];
    const uint32_t SQ = smem_u32(smraw);
    const uint32_t SK = SQ + ATILE;
    const uint32_t SV = SK + ATILE;

    const int bid = blockIdx.x;
    const int h   = bid % NHD;
    const int l   = (bid / NHD) % LWIN;
    const int b   = bid / (NHD * LWIN);
    const int wy  = l / NWIN;
    const int wx  = l % NWIN;
    const int t   = threadIdx.x;
    const int warp = t >> 5;
    const int lane = t & 31;
    const int g    = lane >> 2;
    const int tg   = lane & 3;

    // ---- stage Q,K,V rows via cp.async; zero pad rows ----
    {
        const int r = t;   // 0..223
        bool valid = false;
        int tok = 0;
        if (r < NW) {
            int ly = r / WIN, lx = r % WIN;
            int gy = wy * WIN + ly, gx = wx * WIN + lx;
            if (gy < Hh && gx < Wd) { valid = true; tok = gy * Wd + gx; }
        }
        if (valid) {
            const __half* base = qkv + ((size_t)b * NPOS + tok) * C3 + h * HD;
#pragma unroll
            for (int ch = 0; ch < 8; ch++) {
                cp16(SQ + r * ARS + ch * 16, base + ch * 8);
                cp16(SK + r * ARS + ch * 16, base + Cc + ch * 8);
                cp16(SV + r * ARS + ch * 16, base + 2 * Cc + ch * 8);
            }
        } else {
#pragma unroll
            for (int ch = 0; ch < 8; ch++) {
                asm volatile("st.shared.v4.b32 [%0], {%1,%1,%1,%1};" :: "r"(SQ + r * ARS + ch * 16), "r"(0) : "memory");
                asm volatile("st.shared.v4.b32 [%0], {%1,%1,%1,%1};" :: "r"(SK + r * ARS + ch * 16), "r"(0) : "memory");
                asm volatile("st.shared.v4.b32 [%0], {%1,%1,%1,%1};" :: "r"(SV + r * ARS + ch * 16), "r"(0) : "memory");
            }
        }
        asm volatile("cp.async.commit_group;" ::: "memory");
        cp_wait<0>();
    }
    __syncthreads();

    const int wr = warp * 32;

    // Q fragments for this warp's 32 rows (held all kernel)
    uint32_t qf[2][4][4];
#pragma unroll
    for (int mt = 0; mt < 2; mt++)
#pragma unroll
        for (int kk = 0; kk < 4; kk++) {
            uint32_t addr = SQ + (uint32_t)(wr + mt * 16 + (lane & 15)) * ARS +
                            kk * 32 + ((lane >> 4) & 1) * 16;
            ldsm4a(qf[mt][kk], addr);
        }

    float oacc[2][8][4];
#pragma unroll
    for (int mt = 0; mt < 2; mt++)
#pragma unroll
        for (int nt = 0; nt < 8; nt++)
#pragma unroll
            for (int e = 0; e < 4; e++) oacc[mt][nt][e] = 0.f;
    float rs[2][2] = {{0.f, 0.f}, {0.f, 0.f}};

#pragma unroll 1
    for (int c = 0; c < 7; c++) {
        const int kb = c * 32;

        // ---- S = Q @ K^T ----
        float sa[2][4][4];
#pragma unroll
        for (int mt = 0; mt < 2; mt++)
#pragma unroll
            for (int nt = 0; nt < 4; nt++)
#pragma unroll
                for (int e = 0; e < 4; e++) sa[mt][nt][e] = 0.f;

#pragma unroll
        for (int kk = 0; kk < 4; kk++) {
#pragma unroll
            for (int nn = 0; nn < 2; nn++) {
                uint32_t kf[4];
                uint32_t addr = SK + (uint32_t)(kb + nn * 16 + (lane & 7) +
                                                ((lane >> 4) & 1) * 8) * ARS +
                                ((lane >> 3) & 1) * 16 + kk * 32;
                ldsm4a(kf, addr);
#pragma unroll
                for (int mt = 0; mt < 2; mt++) {
                    mma_f16(sa[mt][2 * nn + 0], qf[mt][kk], kf + 0);
                    mma_f16(sa[mt][2 * nn + 1], qf[mt][kk], kf + 2);
                }
            }
        }

        // ---- exp + mask + rowsum ----
#pragma unroll
        for (int mt = 0; mt < 2; mt++)
#pragma unroll
            for (int nt = 0; nt < 4; nt++) {
#pragma unroll
                for (int e = 0; e < 4; e++) {
                    float p = __expf(sa[mt][nt][e]);
                    if (c == 6) {
                        int col = kb + nt * 8 + 2 * tg + (e & 1);
                        if (col >= NW) p = 0.f;
                    }
                    sa[mt][nt][e] = p;
                }
                rs[mt][0] += sa[mt][nt][0] + sa[mt][nt][1];
                rs[mt][1] += sa[mt][nt][2] + sa[mt][nt][3];
            }

        // ---- O += P @ V ----
#pragma unroll
        for (int j = 0; j < 2; j++) {
            uint32_t ap[2][4];
#pragma unroll
            for (int mt = 0; mt < 2; mt++) {
                __half2 a0 = __floats2half2_rn(sa[mt][2 * j][0], sa[mt][2 * j][1]);
                __half2 a1 = __floats2half2_rn(sa[mt][2 * j][2], sa[mt][2 * j][3]);
                __half2 a2 = __floats2half2_rn(sa[mt][2 * j + 1][0], sa[mt][2 * j + 1][1]);
                __half2 a3 = __floats2half2_rn(sa[mt][2 * j + 1][2], sa[mt][2 * j + 1][3]);
                ap[mt][0] = *(uint32_t*)&a0;
                ap[mt][1] = *(uint32_t*)&a1;
                ap[mt][2] = *(uint32_t*)&a2;
                ap[mt][3] = *(uint32_t*)&a3;
            }
#pragma unroll
            for (int nn = 0; nn < 4; nn++) {
                uint32_t vf[4];
                uint32_t addr = SV + (uint32_t)(kb + j * 16 + (lane & 15)) * ARS +
                                nn * 32 + ((lane >> 4) & 1) * 16;
                ldsm4t(vf, addr);
#pragma unroll
                for (int mt = 0; mt < 2; mt++) {
                    mma_f16(oacc[mt][2 * nn + 0], ap[mt], vf + 0);
                    mma_f16(oacc[mt][2 * nn + 1], ap[mt], vf + 2);
                }
            }
        }
    }

    // ---- rowsum reduce across quad ----
#pragma unroll
    for (int mt = 0; mt < 2; mt++)
#pragma unroll
        for (int e = 0; e < 2; e++) {
            float v = rs[mt][e];
            v += __shfl_xor_sync(0xffffffff, v, 1);
            v += __shfl_xor_sync(0xffffffff, v, 2);
            rs[mt][e] = 1.f / v;
        }

    // ---- epilogue: normalize -> fp16 store ----
#pragma unroll
    for (int mt = 0; mt < 2; mt++) {
#pragma unroll
        for (int e = 0; e < 2; e++) {
            int r = wr + mt * 16 + g + e * 8;
            if (r >= NW) continue;
            int ly = r / WIN, lx = r % WIN;
            int gy = wy * WIN + ly, gx = wx * WIN + lx;
            if (gy >= Hh || gx >= Wd) continue;
            size_t off = ((size_t)b * NPOS + gy * Wd + gx) * Cc + h * HD + 2 * tg;
            float inv = rs[mt][e];
#pragma unroll
            for (int nt = 0; nt < 8; nt++) {
                __half2 v = __floats2half2_rn(oacc[mt][nt][e * 2 + 0] * inv,
                                              oacc[mt][nt][e * 2 + 1] * inv);
                *(__half2*)(att + off + nt * 8) = v;
            }
        }
    }
}

// ---------------------------------------------------------------------------
extern "C" void kernel_launch(void* const* d_in, const int* in_sizes, int n_in,
                              void* d_out, int out_size) {
    const float* x     = (const float*)d_in[0];
    const float* Wqkv  = (const float*)d_in[1];
    const float* Wproj = (const float*)d_in[2];
    const float* bproj = (const float*)d_in[3];
    float* out = (float*)d_out;

    __half *qkv, *xh, *att, *wq, *wp;
    cudaGetSymbolAddress((void**)&qkv, g_qkv);
    cudaGetSymbolAddress((void**)&xh,  g_xh);
    cudaGetSymbolAddress((void**)&att, g_att);
    cudaGetSymbolAddress((void**)&wq,  g_wq);
    cudaGetSymbolAddress((void**)&wp,  g_wp);

    cudaFuncSetAttribute(gemm_hmma<__half>, cudaFuncAttributeMaxDynamicSharedMemorySize, GSM);
    cudaFuncSetAttribute(gemm_hmma<float>,  cudaFuncAttributeMaxDynamicSharedMemorySize, GSM);
    cudaFuncSetAttribute(attn_tc, cudaFuncAttributeMaxDynamicSharedMemorySize, ASMEM);

    // Prep
    {
        int n4 = Mrows * Cc / 4;
        conv_half<<<(n4 + 255) / 256, 256>>>(x, xh, n4);
        dim3 tb(32, 8);
        transpose_half<<<dim3(C3 / 32, Cc / 32), tb>>>(Wqkv, wq, Cc, C3);
        transpose_half<<<dim3(Cc / 32, Cc / 32), tb>>>(Wproj, wp, Cc, Cc);
    }

    // GEMM1: qkv(fp16) = x @ Wqkv, q cols pre-scaled by 1/8
    gemm_hmma<__half><<<dim3(C3 / 128, Mrows / 128), 256, GSM>>>(
        xh, wq, nullptr, qkv, Mrows, C3, Cc, 0.125f, Cc);

    // Tensor-core attention -> fp16 output
    attn_tc<<<Bn * LWIN * NHD, 224, ASMEM>>>(qkv, att);

    // GEMM2: out(fp32) = att @ Wproj + bias
    gemm_hmma<float><<<dim3(Cc / 128, Mrows / 128), 256, GSM>>>(
        att, wp, bproj, out, Mrows, Cc, Cc, 1.f, 0);
}